// round 1
// baseline (speedup 1.0000x reference)
#include <cuda_runtime.h>
#include <cuda_bf16.h>
#include <math.h>
#include <stdint.h>

#define N_SEQS   2048
#define SEQ_LEN  512
#define N_AA     20
#define M_MI     100
#define N_PAIRS  4950                    // 100*99/2 upper triangle
#define OUT_PSSM 0
#define OUT_CONS (SEQ_LEN * N_AA)        // 10240
#define OUT_MI   (OUT_CONS + SEQ_LEN)    // 10752
#define OUT_TOTAL (OUT_MI + SEQ_LEN * SEQ_LEN)  // 272896

// Scratch (no allocations allowed)
__device__ unsigned char g_colpack[M_MI * N_SEQS];   // column-major int8 copy of msa[:, :100]
__device__ int           g_counts[SEQ_LEN * 21];     // per-position AA counts (incl. gap)

// ---------------------------------------------------------------------------
// Zero output + scratch counts
// ---------------------------------------------------------------------------
__global__ void zero_kernel(float* __restrict__ out) {
    int idx = blockIdx.x * blockDim.x + threadIdx.x;
    int stride = gridDim.x * blockDim.x;
    float4* o4 = (float4*)out;
    const int n4 = OUT_TOTAL / 4;
    float4 z = make_float4(0.f, 0.f, 0.f, 0.f);
    for (int v = idx; v < n4; v += stride) o4[v] = z;
    for (int v = idx; v < SEQ_LEN * 21; v += stride) g_counts[v] = 0;
}

// ---------------------------------------------------------------------------
// Pack first 100 columns of msa into int8, column-major
// ---------------------------------------------------------------------------
__global__ void pack_kernel(const int* __restrict__ msa) {
    int i = blockIdx.x;  // column 0..99
    for (int n = threadIdx.x; n < N_SEQS; n += blockDim.x)
        g_colpack[i * N_SEQS + n] = (unsigned char)msa[n * SEQ_LEN + i];
}

// ---------------------------------------------------------------------------
// Per-position AA counts (stage 1: smem partials, merge via global atomics)
// grid (16 col-chunks of 32, 8 row-chunks of 256), 256 threads
// ---------------------------------------------------------------------------
__global__ void count_kernel(const int* __restrict__ msa) {
    __shared__ int cnt[32][21];
    int tid = threadIdx.x;
    for (int v = tid; v < 32 * 21; v += blockDim.x) ((int*)cnt)[v] = 0;
    __syncthreads();

    int lane = tid & 31;
    int col  = blockIdx.x * 32 + lane;
    int rbase = blockIdx.y * 256;
    for (int r = rbase + (tid >> 5); r < rbase + 256; r += 8) {
        int c = msa[r * SEQ_LEN + col];   // coalesced 128B per warp
        atomicAdd(&cnt[lane][c], 1);
    }
    __syncthreads();
    for (int v = tid; v < 32 * 21; v += blockDim.x) {
        int c = ((int*)cnt)[v];
        if (c) atomicAdd(&g_counts[(blockIdx.x * 32 + v / 21) * 21 + (v % 21)], c);
    }
}

// ---------------------------------------------------------------------------
// PSSM + conservation from counts. One thread per position.
// ---------------------------------------------------------------------------
__global__ void pssm_kernel(float* __restrict__ out, const float* __restrict__ pc) {
    int p = blockIdx.x * blockDim.x + threadIdx.x;
    if (p >= SEQ_LEN) return;
    float pcount = 0.01f * pc[0];
    int cts[20];
    int total = 0;
#pragma unroll
    for (int a = 0; a < 20; a++) { cts[a] = g_counts[p * 21 + a]; total += cts[a]; }

    float inv_den = 1.0f / ((float)N_SEQS + pcount * 20.0f);
#pragma unroll
    for (int a = 0; a < 20; a++) {
        float freq = ((float)cts[a] + pcount) * inv_den;
        out[OUT_PSSM + p * 20 + a] = logf(freq * 20.0f + 1e-10f);
    }
    float tinv = 1.0f / fmaxf((float)total, 1.0f);
    float ent = 0.0f;
#pragma unroll
    for (int a = 0; a < 20; a++) {
        float f = (float)cts[a] * tinv;
        ent -= f * log2f(f + 1e-10f);
    }
    out[OUT_CONS + p] = (total > 0) ? (1.0f - ent / 4.321928094887362f) : 0.0f;
}

// ---------------------------------------------------------------------------
// MI: one warp per (i<j) pair. Private 21x21 smem histogram (gap-inclusive,
// branch-free atomics). Epilogue uses an integer log2 LUT: no MUFU in hot path.
// ---------------------------------------------------------------------------
__global__ __launch_bounds__(256) void mi_kernel(float* __restrict__ mi_out) {
    __shared__ int   hist[8][441];
    __shared__ float lut[2049];       // log2 of integers 0..2048
    __shared__ float slra[8][20];     // log2(row marginal) per warp
    __shared__ float slcb[8][20];     // log2(col marginal) per warp

    int tid = threadIdx.x, wid = tid >> 5, lane = tid & 31;
    for (int v = tid; v < 2049; v += blockDim.x) lut[v] = log2f((float)v);
    __syncthreads();

    int pid = blockIdx.x * 8 + wid;
    if (pid >= N_PAIRS) return;

    // Decode upper-triangle pair index -> (i, j), i < j, using T(i) = i*(199-i)/2
    float d = sqrtf(39601.0f - 8.0f * (float)pid);
    int i = (int)((199.0f - d) * 0.5f);
    if (i < 0) i = 0;
    if (i > 98) i = 98;
    while ((((i + 1) * (199 - (i + 1))) >> 1) <= pid) ++i;
    while (((i * (199 - i)) >> 1) > pid) --i;
    int j = pid - ((i * (199 - i)) >> 1) + i + 1;

    int* h = hist[wid];
    for (int v = lane; v < 441; v += 32) h[v] = 0;
    __syncwarp();

    const uint32_t* ca = (const uint32_t*)(g_colpack + i * N_SEQS);
    const uint32_t* cb = (const uint32_t*)(g_colpack + j * N_SEQS);
#pragma unroll 4
    for (int it = lane; it < N_SEQS / 4; it += 32) {
        uint32_t wa = ca[it], wb = cb[it];   // coalesced; L1/L2 resident
#pragma unroll
        for (int s = 0; s < 4; s++) {
            int a = (wa >> (8 * s)) & 255;
            int b = (wb >> (8 * s)) & 255;
            atomicAdd(&h[a * 21 + b], 1);    // spread-address smem atomic
        }
    }
    __syncwarp();

    // Marginals over the 20x20 non-gap block (integers)
    int rs = 0, cs = 0;
    if (lane < 20) {
#pragma unroll
        for (int b = 0; b < 20; b++) { rs += h[lane * 21 + b]; cs += h[b * 21 + lane]; }
        slra[wid][lane] = lut[rs];   // only read under H>0 guard => rs>0 there
        slcb[wid][lane] = lut[cs];
    }
    int tv = (lane < 20) ? rs : 0;
#pragma unroll
    for (int off = 16; off; off >>= 1) tv += __shfl_down_sync(0xffffffffu, tv, off);
    int tot = __shfl_sync(0xffffffffu, tv, 0);
    __syncwarp();

    int tots = (tot > 0) ? tot : 1;
    float lt = lut[tots];
    float acc = 0.0f;
    for (int c = lane; c < 400; c += 32) {
        int a = (c * 3277) >> 16;   // c / 20 for c < 400
        int b = c - a * 20;
        int H = h[a * 21 + b];
        if (H > 0)
            acc += (float)H * (lut[H] - slra[wid][a] - slcb[wid][b] + lt);
    }
#pragma unroll
    for (int off = 16; off; off >>= 1) acc += __shfl_down_sync(0xffffffffu, acc, off);

    if (lane == 0) {
        float mi = (tot > 0) ? acc / (float)tots : 0.0f;
        mi_out[i * SEQ_LEN + j] = mi;
        mi_out[j * SEQ_LEN + i] = mi;
    }
}

// ---------------------------------------------------------------------------
extern "C" void kernel_launch(void* const* d_in, const int* in_sizes, int n_in,
                              void* d_out, int out_size) {
    const int*   msa = (const int*)d_in[0];
    const float* pc  = (const float*)d_in[1];
    float*       out = (float*)d_out;

    zero_kernel<<<256, 256>>>(out);                  // zero output + g_counts
    pack_kernel<<<M_MI, 256>>>(msa);                 // int8 column pack
    count_kernel<<<dim3(16, 8), 256>>>(msa);         // per-position counts
    pssm_kernel<<<2, 256>>>(out, pc);                // pssm + conservation
    mi_kernel<<<(N_PAIRS + 7) / 8, 256>>>(out + OUT_MI);  // pairwise MI
}

// round 2
// speedup vs baseline: 1.1636x; 1.1636x over previous
#include <cuda_runtime.h>
#include <cuda_bf16.h>
#include <math.h>
#include <stdint.h>

#define N_SEQS   2048
#define SEQ_LEN  512
#define N_AA     20
#define M_MI     100
#define N_PAIRS  4950                    // 100*99/2 upper triangle
#define OUT_PSSM 0
#define OUT_CONS (SEQ_LEN * N_AA)        // 10240
#define OUT_MI   (OUT_CONS + SEQ_LEN)    // 10752
#define OUT_TOTAL (OUT_MI + SEQ_LEN * SEQ_LEN)  // 272896

// Scratch (no dynamic allocation allowed)
__device__ unsigned char g_colpack[M_MI * N_SEQS];   // column-major int8 msa[:, :100]
__device__ int           g_counts[SEQ_LEN * 21];     // per-position AA counts (incl gap)

// ---------------------------------------------------------------------------
// Fused: per-position AA counts + int8 column pack for MI columns.
// grid (16 col-chunks of 32, 8 row-chunks of 256), 256 threads.
// Warp w owns rows [rbase + 32w, +32); lane = column -> coalesced 128B reads.
// Each thread packs 4 consecutive rows of its column into one uint32 store.
// g_counts pre-zeroed by a memset node.
// ---------------------------------------------------------------------------
__global__ __launch_bounds__(256) void count_pack_kernel(const int* __restrict__ msa) {
    __shared__ int cnt[32][21];
    int tid = threadIdx.x, lane = tid & 31, w = tid >> 5;
    for (int v = tid; v < 32 * 21; v += 256) ((int*)cnt)[v] = 0;
    __syncthreads();

    int col   = blockIdx.x * 32 + lane;
    int rbase = blockIdx.y * 256 + w * 32;
    bool dopack = (col < M_MI);

#pragma unroll
    for (int k = 0; k < 32; k += 4) {
        uint32_t packed = 0;
#pragma unroll
        for (int s = 0; s < 4; s++) {
            int c = msa[(rbase + k + s) * SEQ_LEN + col];
            atomicAdd(&cnt[lane][c], 1);               // addr = lane*21+c: conflict-free across lanes
            packed |= (uint32_t)c << (8 * s);
        }
        if (dopack)
            *(uint32_t*)&g_colpack[col * N_SEQS + rbase + k] = packed;
    }
    __syncthreads();

    for (int v = tid; v < 32 * 21; v += 256) {
        int c = ((int*)cnt)[v];
        if (c) atomicAdd(&g_counts[(blockIdx.x * 32 + v / 21) * 21 + (v % 21)], c);
    }
}

// ---------------------------------------------------------------------------
// PSSM + conservation: ONE WARP PER POSITION (lane = amino acid).
// 512 warps -> 64 blocks x 256 threads. 2 MUFU logs per lane.
// ---------------------------------------------------------------------------
__global__ __launch_bounds__(256) void pssm_kernel(float* __restrict__ out, const float* __restrict__ pc) {
    int gtid = blockIdx.x * blockDim.x + threadIdx.x;
    int p = gtid >> 5, lane = gtid & 31;
    if (p >= SEQ_LEN) return;

    int ct = (lane < 20) ? g_counts[p * 21 + lane] : 0;

    // total over 20 lanes (butterfly)
    int t = ct;
#pragma unroll
    for (int off = 16; off; off >>= 1) t += __shfl_xor_sync(0xffffffffu, t, off);
    int total = t;

    float pcount = 0.01f * pc[0];
    float inv_den = 1.0f / ((float)N_SEQS + pcount * 20.0f);
    float tinv = 1.0f / fmaxf((float)total, 1.0f);

    float ent = 0.0f;
    if (lane < 20) {
        float freq = ((float)ct + pcount) * inv_den;
        out[OUT_PSSM + p * 20 + lane] = logf(freq * 20.0f + 1e-10f);
        float f = (float)ct * tinv;
        ent = -f * log2f(f + 1e-10f);
    }
#pragma unroll
    for (int off = 16; off; off >>= 1) ent += __shfl_xor_sync(0xffffffffu, ent, off);
    if (lane == 0)
        out[OUT_CONS + p] = (total > 0) ? (1.0f - ent * (1.0f / 4.321928094887362f)) : 0.0f;
}

// ---------------------------------------------------------------------------
// MI: one warp per (i<j) pair. 400-bin (20x20) smem histogram — gap events
// (a==20 || b==20) contribute nothing in the 20-class one-hot reference, so
// they are predicated out of the atomic entirely (~9.3% fewer ATOMS lanes).
// Integer log2 LUT kills all MUFU in the epilogue.
// ---------------------------------------------------------------------------
__global__ __launch_bounds__(256) void mi_kernel(float* __restrict__ mi_out) {
    __shared__ int   hist[8][400];
    __shared__ float lut[2049];       // log2(0..2048)
    __shared__ float slra[8][20];
    __shared__ float slcb[8][20];

    int tid = threadIdx.x, wid = tid >> 5, lane = tid & 31;
    for (int v = tid; v < 2049; v += 256) lut[v] = log2f((float)v);
    __syncthreads();

    int pid = blockIdx.x * 8 + wid;
    if (pid >= N_PAIRS) return;

    // Decode upper-triangle pair index -> (i, j), i < j; T(i) = i*(199-i)/2
    float d = sqrtf(39601.0f - 8.0f * (float)pid);
    int i = (int)((199.0f - d) * 0.5f);
    if (i < 0) i = 0;
    if (i > 98) i = 98;
    while ((((i + 1) * (199 - (i + 1))) >> 1) <= pid) ++i;
    while (((i * (199 - i)) >> 1) > pid) --i;
    int j = pid - ((i * (199 - i)) >> 1) + i + 1;

    int* h = hist[wid];
    for (int v = lane; v < 400; v += 32) h[v] = 0;
    __syncwarp();

    const uint4* ca = (const uint4*)(g_colpack + i * N_SEQS);
    const uint4* cb = (const uint4*)(g_colpack + j * N_SEQS);
#pragma unroll
    for (int it = lane; it < N_SEQS / 16; it += 32) {   // 4 iterations/lane, LDG.128
        uint4 va = ca[it], vb = cb[it];
        const uint32_t wa_[4] = {va.x, va.y, va.z, va.w};
        const uint32_t wb_[4] = {vb.x, vb.y, vb.z, vb.w};
#pragma unroll
        for (int q = 0; q < 4; q++) {
            uint32_t wa = wa_[q], wb = wb_[q];
#pragma unroll
            for (int s = 0; s < 4; s++) {
                int a = (wa >> (8 * s)) & 255;
                int b = (wb >> (8 * s)) & 255;
                if (a < 20 && b < 20)
                    atomicAdd(&h[a * 20 + b], 1);
            }
        }
    }
    __syncwarp();

    // Integer marginals over the 20x20 block
    int rs = 0, cs = 0;
    if (lane < 20) {
#pragma unroll
        for (int b = 0; b < 20; b++) { rs += h[lane * 20 + b]; cs += h[b * 20 + lane]; }
        slra[wid][lane] = lut[rs];
        slcb[wid][lane] = lut[cs];
    }
    int tv = (lane < 20) ? rs : 0;
#pragma unroll
    for (int off = 16; off; off >>= 1) tv += __shfl_xor_sync(0xffffffffu, tv, off);
    int tot = tv;
    __syncwarp();

    int tots = (tot > 0) ? tot : 1;
    float lt = lut[tots];
    float acc = 0.0f;
    for (int c = lane; c < 400; c += 32) {
        int H = h[c];
        if (H > 0) {
            int a = (c * 3277) >> 16;   // c / 20 for c < 400
            int b = c - a * 20;
            acc += (float)H * (lut[H] - slra[wid][a] - slcb[wid][b] + lt);
        }
    }
#pragma unroll
    for (int off = 16; off; off >>= 1) acc += __shfl_xor_sync(0xffffffffu, acc, off);

    if (lane == 0) {
        float mi = (tot > 0) ? acc / (float)tots : 0.0f;
        mi_out[i * SEQ_LEN + j] = mi;
        mi_out[j * SEQ_LEN + i] = mi;
    }
}

// ---------------------------------------------------------------------------
extern "C" void kernel_launch(void* const* d_in, const int* in_sizes, int n_in,
                              void* d_out, int out_size) {
    const int*   msa = (const int*)d_in[0];
    const float* pc  = (const float*)d_in[1];
    float*       out = (float*)d_out;

    static void* counts_addr = nullptr;
    if (!counts_addr) cudaGetSymbolAddress(&counts_addr, g_counts);

    cudaMemsetAsync(out, 0, OUT_TOTAL * sizeof(float));          // MI padding + diag zeros
    cudaMemsetAsync(counts_addr, 0, SEQ_LEN * 21 * sizeof(int));

    count_pack_kernel<<<dim3(16, 8), 256>>>(msa);                // counts + column pack
    mi_kernel<<<(N_PAIRS + 7) / 8, 256>>>(out + OUT_MI);         // pairwise MI (dominant)
    pssm_kernel<<<64, 256>>>(out, pc);                           // pssm + conservation
}

// round 3
// speedup vs baseline: 1.3956x; 1.1994x over previous
#include <cuda_runtime.h>
#include <cuda_bf16.h>
#include <math.h>
#include <stdint.h>

#define N_SEQS   2048
#define SEQ_LEN  512
#define N_AA     20
#define M_MI     100
#define N_PAIRS  4950                    // 100*99/2 upper triangle
#define OUT_PSSM 0
#define OUT_CONS (SEQ_LEN * N_AA)        // 10240
#define OUT_MI   (OUT_CONS + SEQ_LEN)    // 10752
#define OUT_TOTAL (OUT_MI + SEQ_LEN * SEQ_LEN)  // 272896

// Scratch (no dynamic allocation allowed)
__device__ unsigned char g_colpack[128 * N_SEQS];    // column-major int8 msa[:, :128] (100 used)
__device__ int           g_counts[SEQ_LEN * 21];     // per-position AA counts (incl gap)

// ---------------------------------------------------------------------------
// Pack columns 0..99 into int8 column-major (coalesced reads via lane=column).
// grid (4, 32) x 256: warp w of CTA (bx,by) covers cols bx*32+lane,
// rows [by*64 + w*8, +8). Each thread packs 8 rows -> two uint32 stores.
// ---------------------------------------------------------------------------
__global__ __launch_bounds__(256) void pack_kernel(const int* __restrict__ msa) {
    int tid = threadIdx.x, lane = tid & 31, w = tid >> 5;
    int col   = blockIdx.x * 32 + lane;
    int rbase = blockIdx.y * 64 + w * 8;
    bool dopack = (col < M_MI);

    uint32_t p0 = 0, p1 = 0;
#pragma unroll
    for (int s = 0; s < 4; s++) {
        p0 |= (uint32_t)msa[(rbase + s)     * SEQ_LEN + col] << (8 * s);
        p1 |= (uint32_t)msa[(rbase + 4 + s) * SEQ_LEN + col] << (8 * s);
    }
    if (dopack) {
        *(uint32_t*)&g_colpack[col * N_SEQS + rbase]     = p0;
        *(uint32_t*)&g_colpack[col * N_SEQS + rbase + 4] = p1;
    }
}

// ---------------------------------------------------------------------------
// Per-position AA counts WITHOUT atomics in the hot loop: per-warp replica
// histograms make each counter private to one (warp, lane) -> plain smem RMW.
// grid (16, 16) x 256: 32 cols x 128 rows per CTA, 16 rows per thread.
// g_counts pre-zeroed by a memset node; merged via global atomics.
// ---------------------------------------------------------------------------
__global__ __launch_bounds__(256) void count_kernel(const int* __restrict__ msa) {
    __shared__ int cnt[8][32][21];     // [warp][lane(col)][symbol]
    int tid = threadIdx.x, lane = tid & 31, w = tid >> 5;
    for (int v = tid; v < 8 * 32 * 21; v += 256) ((int*)cnt)[v] = 0;
    __syncthreads();

    int col   = blockIdx.x * 32 + lane;
    int rbase = blockIdx.y * 128 + w * 16;
    int* my = cnt[w][lane];
#pragma unroll
    for (int s = 0; s < 16; s++) {
        int c = msa[(rbase + s) * SEQ_LEN + col];   // coalesced 128B per warp
        my[c] += 1;                                  // private: no atomic needed
    }
    __syncthreads();

    // Merge 8 replicas and push to global counts
    for (int v = tid; v < 32 * 21; v += 256) {
        int l = v / 21, c = v % 21;
        int s = 0;
#pragma unroll
        for (int ww = 0; ww < 8; ww++) s += cnt[ww][l][c];
        if (s) atomicAdd(&g_counts[(blockIdx.x * 32 + l) * 21 + c], s);
    }
}

// ---------------------------------------------------------------------------
// PSSM + conservation: one warp per position (lane = amino acid).
// ---------------------------------------------------------------------------
__global__ __launch_bounds__(256) void pssm_kernel(float* __restrict__ out, const float* __restrict__ pc) {
    int gtid = blockIdx.x * blockDim.x + threadIdx.x;
    int p = gtid >> 5, lane = gtid & 31;
    if (p >= SEQ_LEN) return;

    int ct = (lane < 20) ? g_counts[p * 21 + lane] : 0;

    int t = ct;
#pragma unroll
    for (int off = 16; off; off >>= 1) t += __shfl_xor_sync(0xffffffffu, t, off);
    int total = t;

    float pcount = 0.01f * pc[0];
    float inv_den = 1.0f / ((float)N_SEQS + pcount * 20.0f);
    float tinv = 1.0f / fmaxf((float)total, 1.0f);

    float ent = 0.0f;
    if (lane < 20) {
        float freq = ((float)ct + pcount) * inv_den;
        out[OUT_PSSM + p * 20 + lane] = logf(freq * 20.0f + 1e-10f);
        float f = (float)ct * tinv;
        ent = -f * log2f(f + 1e-10f);
    }
#pragma unroll
    for (int off = 16; off; off >>= 1) ent += __shfl_xor_sync(0xffffffffu, ent, off);
    if (lane == 0)
        out[OUT_CONS + p] = (total > 0) ? (1.0f - ent * (1.0f / 4.321928094887362f)) : 0.0f;
}

// ---------------------------------------------------------------------------
// MI: one warp per (i<j) pair. 400-bin smem histogram; gap events predicated
// out (contribute nothing under 20-class one-hot). Integer log2 LUT epilogue.
// ---------------------------------------------------------------------------
__global__ __launch_bounds__(256) void mi_kernel(float* __restrict__ mi_out) {
    __shared__ int   hist[8][400];
    __shared__ float lut[2049];       // log2(0..2048)
    __shared__ float slra[8][20];
    __shared__ float slcb[8][20];

    int tid = threadIdx.x, wid = tid >> 5, lane = tid & 31;
    for (int v = tid; v < 2049; v += 256) lut[v] = log2f((float)v);
    __syncthreads();

    int pid = blockIdx.x * 8 + wid;
    if (pid >= N_PAIRS) return;

    // Decode upper-triangle pair index -> (i, j), i < j; T(i) = i*(199-i)/2
    float d = sqrtf(39601.0f - 8.0f * (float)pid);
    int i = (int)((199.0f - d) * 0.5f);
    if (i < 0) i = 0;
    if (i > 98) i = 98;
    while ((((i + 1) * (199 - (i + 1))) >> 1) <= pid) ++i;
    while (((i * (199 - i)) >> 1) > pid) --i;
    int j = pid - ((i * (199 - i)) >> 1) + i + 1;

    int* h = hist[wid];
    for (int v = lane; v < 400; v += 32) h[v] = 0;
    __syncwarp();

    const uint4* ca = (const uint4*)(g_colpack + i * N_SEQS);
    const uint4* cb = (const uint4*)(g_colpack + j * N_SEQS);
#pragma unroll
    for (int it = lane; it < N_SEQS / 16; it += 32) {   // 4 iterations/lane, LDG.128
        uint4 va = ca[it], vb = cb[it];
        const uint32_t wa_[4] = {va.x, va.y, va.z, va.w};
        const uint32_t wb_[4] = {vb.x, vb.y, vb.z, vb.w};
#pragma unroll
        for (int q = 0; q < 4; q++) {
            uint32_t wa = wa_[q], wb = wb_[q];
#pragma unroll
            for (int s = 0; s < 4; s++) {
                int a = (wa >> (8 * s)) & 255;
                int b = (wb >> (8 * s)) & 255;
                if (a < 20 && b < 20)
                    atomicAdd(&h[a * 20 + b], 1);
            }
        }
    }
    __syncwarp();

    // Integer marginals over the 20x20 block
    int rs = 0, cs = 0;
    if (lane < 20) {
#pragma unroll
        for (int b = 0; b < 20; b++) { rs += h[lane * 20 + b]; cs += h[b * 20 + lane]; }
        slra[wid][lane] = lut[rs];
        slcb[wid][lane] = lut[cs];
    }
    int tv = (lane < 20) ? rs : 0;
#pragma unroll
    for (int off = 16; off; off >>= 1) tv += __shfl_xor_sync(0xffffffffu, tv, off);
    int tot = tv;
    __syncwarp();

    int tots = (tot > 0) ? tot : 1;
    float lt = lut[tots];
    float acc = 0.0f;
    for (int c = lane; c < 400; c += 32) {
        int H = h[c];
        if (H > 0) {
            int a = (c * 3277) >> 16;   // c / 20 for c < 400
            int b = c - a * 20;
            acc += (float)H * (lut[H] - slra[wid][a] - slcb[wid][b] + lt);
        }
    }
#pragma unroll
    for (int off = 16; off; off >>= 1) acc += __shfl_xor_sync(0xffffffffu, acc, off);

    if (lane == 0) {
        float mi = (tot > 0) ? acc / (float)tots : 0.0f;
        mi_out[i * SEQ_LEN + j] = mi;
        mi_out[j * SEQ_LEN + i] = mi;
    }
}

// ---------------------------------------------------------------------------
// Launch: pack -> fork -> [mi on main stream] || [count + pssm on side stream]
// -> join. All capturable (event fork/join, async memsets, no allocations).
// ---------------------------------------------------------------------------
extern "C" void kernel_launch(void* const* d_in, const int* in_sizes, int n_in,
                              void* d_out, int out_size) {
    const int*   msa = (const int*)d_in[0];
    const float* pc  = (const float*)d_in[1];
    float*       out = (float*)d_out;

    static void* counts_addr = nullptr;
    static cudaStream_t s1;
    static cudaEvent_t e_fork, e_join;
    static bool init = false;
    if (!init) {
        cudaGetSymbolAddress(&counts_addr, g_counts);
        cudaStreamCreateWithFlags(&s1, cudaStreamNonBlocking);
        cudaEventCreateWithFlags(&e_fork, cudaEventDisableTiming);
        cudaEventCreateWithFlags(&e_join, cudaEventDisableTiming);
        init = true;
    }

    // Main stream: zero scratch + MI region, pack MI columns
    cudaMemsetAsync(counts_addr, 0, SEQ_LEN * 21 * sizeof(int));
    cudaMemsetAsync(out + OUT_MI, 0, SEQ_LEN * SEQ_LEN * sizeof(float));
    pack_kernel<<<dim3(4, 32), 256>>>(msa);
    cudaEventRecord(e_fork, 0);

    // Side stream: counts + pssm/conservation (independent of pack/mi data,
    // but wait for the counts memset ordered before e_fork)
    cudaStreamWaitEvent(s1, e_fork, 0);
    count_kernel<<<dim3(16, 16), 256, 0, s1>>>(msa);
    pssm_kernel<<<64, 256, 0, s1>>>(out, pc);
    cudaEventRecord(e_join, s1);

    // Main stream: dominant MI kernel runs concurrently with the side stream
    mi_kernel<<<(N_PAIRS + 7) / 8, 256>>>(out + OUT_MI);
    cudaStreamWaitEvent(0, e_join, 0);
}